// round 10
// baseline (speedup 1.0000x reference)
#include <cuda_runtime.h>
#include <cuda_bf16.h>
#include <math.h>
#include <stdint.h>

#define Bz 2
#define Sz 2048
#define Cz 1024
#define Hz 16
#define Dz 64
#define BHz 32

typedef unsigned short u16;

// ---------------------------------------------------------------------------
// Scratch (device globals)
// ---------------------------------------------------------------------------
__device__ float g_q[BHz * Sz * Dz];
__device__ float g_cv[BHz * Sz * Dz];
__device__ float g_Mpart[4 * BHz * Dz * Dz];
__device__ float g_bterm[Bz * Cz];
__device__ float g_c2[Bz * Cz];

// bf16 hi/lo planes
__device__ u16 g_xh[Bz * Sz * Cz], g_xl[Bz * Sz * Cz];
__device__ u16 g_yh[Bz * Sz * Cz], g_yl[Bz * Sz * Cz];
__device__ u16 g_wqh[Cz * Cz], g_wql[Cz * Cz];
__device__ u16 g_wvh[Cz * Cz], g_wvl[Cz * Cz];
__device__ u16 g_wfh[Cz * Cz], g_wfl[Cz * Cz];
__device__ u16 g_vh[BHz * Sz * Dz], g_vl[BHz * Sz * Dz];
__device__ u16 g_wkph[Bz * Cz * Cz], g_wkpl[Bz * Cz * Cz];   // Wk' = wk @ M
__device__ u16 g_w2h[Bz * Cz * Cz], g_w2l[Bz * Cz * Cz];     // W2 = Wk' @ wf

// ---------------------------------------------------------------------------
// Helpers
// ---------------------------------------------------------------------------
__device__ __forceinline__ uint32_t smem_u32(const void* p) {
    return (uint32_t)__cvta_generic_to_shared(p);
}
__device__ __forceinline__ void ldsm4(uint32_t* r, uint32_t a) {
    asm volatile("ldmatrix.sync.aligned.m8n8.x4.shared.b16 {%0,%1,%2,%3},[%4];"
                 : "=r"(r[0]), "=r"(r[1]), "=r"(r[2]), "=r"(r[3]) : "r"(a));
}
__device__ __forceinline__ void ldsm4t(uint32_t* r, uint32_t a) {
    asm volatile("ldmatrix.sync.aligned.m8n8.x4.trans.shared.b16 {%0,%1,%2,%3},[%4];"
                 : "=r"(r[0]), "=r"(r[1]), "=r"(r[2]), "=r"(r[3]) : "r"(a));
}
__device__ __forceinline__ void mma16816(float* d, const uint32_t* a, const uint32_t* b) {
    asm volatile("mma.sync.aligned.m16n8k16.row.col.f32.bf16.bf16.f32 "
                 "{%0,%1,%2,%3},{%4,%5,%6,%7},{%8,%9},{%0,%1,%2,%3};"
                 : "+f"(d[0]), "+f"(d[1]), "+f"(d[2]), "+f"(d[3])
                 : "r"(a[0]), "r"(a[1]), "r"(a[2]), "r"(a[3]), "r"(b[0]), "r"(b[1]));
}
__device__ __forceinline__ void cpa16(uint32_t s, const void* g) {
    asm volatile("cp.async.cg.shared.global [%0], [%1], 16;" :: "r"(s), "l"(g));
}
__device__ __forceinline__ void cpa_commit() {
    asm volatile("cp.async.commit_group;" ::: "memory");
}
__device__ __forceinline__ void cpa_wait1() {
    asm volatile("cp.async.wait_group 1;" ::: "memory");
}
__device__ __forceinline__ void split_pack(float x, float y, uint32_t& hi, uint32_t& lo) {
    __nv_bfloat16 hx = __float2bfloat16_rn(x), hy = __float2bfloat16_rn(y);
    __nv_bfloat16 lx = __float2bfloat16_rn(x - __bfloat162float(hx));
    __nv_bfloat16 ly = __float2bfloat16_rn(y - __bfloat162float(hy));
    hi = ((uint32_t)__bfloat16_as_ushort(hy) << 16) | (uint32_t)__bfloat16_as_ushort(hx);
    lo = ((uint32_t)__bfloat16_as_ushort(ly) << 16) | (uint32_t)__bfloat16_as_ushort(lx);
}
__device__ __forceinline__ float tanh_fast(float x) {
    float xc = fminf(fmaxf(x, -12.0f), 12.0f);
    float e = __expf(2.0f * xc);
    return __fdividef(e - 1.0f, e + 1.0f);
}
__device__ __forceinline__ float mish_f(float v) {
    float sp = (v > 20.0f) ? v : log1pf(expf(v));
    return v * tanhf(sp);
}

// ---------------------------------------------------------------------------
// Kernel 0: fp32 -> bf16 hi/lo plane conversion
// ---------------------------------------------------------------------------
__global__ __launch_bounds__(256) void cvt_kernel(
    const float* __restrict__ src, u16* __restrict__ ph, u16* __restrict__ pl, int n)
{
    int i = (blockIdx.x * 256 + threadIdx.x) * 4;
    if (i < n) {
        float4 v = *(const float4*)&src[i];
        uint32_t h0, l0, h1, l1;
        split_pack(v.x, v.y, h0, l0);
        split_pack(v.z, v.w, h1, l1);
        *(uint2*)&ph[i] = make_uint2(h0, h1);
        *(uint2*)&pl[i] = make_uint2(l0, l1);
    }
}

// ---------------------------------------------------------------------------
// Shared-memory geometry (2-stage double buffering — the R7 known-good loop)
// ---------------------------------------------------------------------------
#define PA 40     // A tile pitch (32 + 8 pad), bf16 elems
#define PB 136    // B tile pitch (128 + 8 pad)
#define PV 72     // v tile pitch (64 + 8 pad)

#define PRJ_APB   10240                 // one A plane: 128*40*2
#define PRJ_BOFF  20480
#define PRJ_BPB   8704                  // one B plane: 32*136*2
#define PRJ_STRIDE 37888
#define PROJ_SMEM (2 * PRJ_STRIDE)

#define CV_APB   10240
#define CV_ABLK  20480
#define CV_BOFF  40960
#define CV_BPB   4608
#define CV_BBLK  9216
#define CV_STRIDE 59392
#define CV_SMEM  (2 * CV_STRIDE)

// stage one (A 128x32, B 32x128) chunk pair of hi/lo planes via cp.async
__device__ __forceinline__ void stage_prj(
    const u16* __restrict__ Ah, const u16* __restrict__ Al,
    const u16* __restrict__ Bh, const u16* __restrict__ Bl,
    uint32_t base, int m0, int n0, int k0, int tid)
{
    int row = tid >> 1, half = tid & 1;
    size_t ga = (size_t)(m0 + row) * Cz + k0 + half * 16;
    uint32_t da = base + (row * PA + half * 16) * 2;
    cpa16(da, Ah + ga);               cpa16(da + 16, Ah + ga + 8);
    cpa16(da + PRJ_APB, Al + ga);     cpa16(da + PRJ_APB + 16, Al + ga + 8);
    int br = tid >> 3, seg = tid & 7;
    size_t gb = (size_t)(k0 + br) * Cz + n0 + seg * 8;
    uint32_t db = base + PRJ_BOFF + (br * PB + seg * 8) * 2;
    cpa16(db, Bh + gb);               cpa16(db + 128, Bh + gb + 64);
    cpa16(db + PRJ_BPB, Bl + gb);     cpa16(db + PRJ_BPB + 128, Bl + gb + 64);
}

// one 32-k chunk of 3-term split MMAs (warp tile 64x32, frags 4x4)
__device__ __forceinline__ void mma_chunk(
    float d[4][4][4], uint32_t Ah, uint32_t Al, uint32_t Bh, uint32_t Bl,
    int pitchB, int wm64, int wn32, int lane)
{
    #pragma unroll
    for (int k16 = 0; k16 < 32; k16 += 16) {
        uint32_t ah[4][4], al[4][4];
        #pragma unroll
        for (int mf = 0; mf < 4; ++mf) {
            int mr = wm64 + mf * 16 + (lane & 15);
            int kc = k16 + ((lane >> 4) << 3);
            ldsm4(ah[mf], Ah + (mr * PA + kc) * 2);
            ldsm4(al[mf], Al + (mr * PA + kc) * 2);
        }
        uint32_t bh[4][2], bl[4][2];
        #pragma unroll
        for (int nf2 = 0; nf2 < 2; ++nf2) {
            int kr = k16 + (lane & 7) + ((lane >> 3) & 1) * 8;
            int nc = wn32 + nf2 * 16 + ((lane >> 4) << 3);
            uint32_t t[4];
            ldsm4t(t, Bh + (kr * pitchB + nc) * 2);
            bh[nf2 * 2][0] = t[0]; bh[nf2 * 2][1] = t[1];
            bh[nf2 * 2 + 1][0] = t[2]; bh[nf2 * 2 + 1][1] = t[3];
            ldsm4t(t, Bl + (kr * pitchB + nc) * 2);
            bl[nf2 * 2][0] = t[0]; bl[nf2 * 2][1] = t[1];
            bl[nf2 * 2 + 1][0] = t[2]; bl[nf2 * 2 + 1][1] = t[3];
        }
        #pragma unroll
        for (int mf = 0; mf < 4; ++mf)
            #pragma unroll
            for (int nf = 0; nf < 4; ++nf) {
                mma16816(d[mf][nf], ah[mf], bh[nf]);
                mma16816(d[mf][nf], ah[mf], bl[nf]);
                mma16816(d[mf][nf], al[mf], bh[nf]);
            }
    }
}

// 2-stage double-buffered mainloop (R7 structure): K = kiters*32
__device__ __forceinline__ void gemm_main(
    float d[4][4][4], const u16* Ah, const u16* Al,
    const u16* Bh, const u16* Bl,
    uint32_t sb, int m0, int n0, int tid, int lane, int wm, int wn, int kiters)
{
    stage_prj(Ah, Al, Bh, Bl, sb, m0, n0, 0, tid);
    cpa_commit();
    for (int i = 0; i < kiters; ++i) {
        const int p = i & 1;
        if (i + 1 < kiters)
            stage_prj(Ah, Al, Bh, Bl, sb + ((i + 1) & 1) * PRJ_STRIDE,
                      m0, n0, (i + 1) * 32, tid);
        cpa_commit();
        cpa_wait1();
        __syncthreads();
        uint32_t base = sb + p * PRJ_STRIDE;
        mma_chunk(d, base, base + PRJ_APB, base + PRJ_BOFF, base + PRJ_BOFF + PRJ_BPB,
                  PB, wm * 64, wn * 32, lane);
        __syncthreads();
    }
}

// ---------------------------------------------------------------------------
// Kernel 1: q/v projections.  which: 0=q(y,wq)->fp32 split-head; 1=v(y,wv)->planes
// ---------------------------------------------------------------------------
__global__ __launch_bounds__(256, 1) void proj_mma(
    const float* __restrict__ bq, const float* __restrict__ bv)
{
    extern __shared__ char smc[];
    const uint32_t sb = smem_u32(smc);
    const int tid = threadIdx.x, lane = tid & 31, wid = tid >> 5;
    const int wm = wid & 1, wn = wid >> 1;
    const int which = blockIdx.z;
    const u16* Bhg = (which == 0) ? g_wqh : g_wvh;
    const u16* Blg = (which == 0) ? g_wql : g_wvl;
    const float* bias = (which == 0) ? bq : bv;
    const int m0 = blockIdx.y * 128, n0 = blockIdx.x * 128;

    float d[4][4][4] = {};
    gemm_main(d, g_yh, g_yl, Bhg, Blg, sb, m0, n0, tid, lane, wm, wn, 32);

    #pragma unroll
    for (int mf = 0; mf < 4; ++mf)
        #pragma unroll
        for (int nf = 0; nf < 4; ++nf) {
            int mr = m0 + wm * 64 + mf * 16 + (lane >> 2);
            int nc = n0 + wn * 32 + nf * 8 + ((lane & 3) << 1);
            float2 bv2 = *(const float2*)&bias[nc];
            int bb = mr >> 11, s = mr & (Sz - 1);
            int h = nc >> 6, dd = nc & 63;
            size_t i0 = (((size_t)bb * Hz + h) * Sz + s) * Dz + dd;
            size_t i1 = (((size_t)bb * Hz + h) * Sz + s + 8) * Dz + dd;
            if (which == 1) {
                uint32_t hi, lo;
                split_pack(d[mf][nf][0] + bv2.x, d[mf][nf][1] + bv2.y, hi, lo);
                *(uint32_t*)&g_vh[i0] = hi; *(uint32_t*)&g_vl[i0] = lo;
                split_pack(d[mf][nf][2] + bv2.x, d[mf][nf][3] + bv2.y, hi, lo);
                *(uint32_t*)&g_vh[i1] = hi; *(uint32_t*)&g_vl[i1] = lo;
            } else {
                *(float2*)&g_q[i0] = make_float2(d[mf][nf][0] + bv2.x, d[mf][nf][1] + bv2.y);
                *(float2*)&g_q[i1] = make_float2(d[mf][nf][2] + bv2.x, d[mf][nf][3] + bv2.y);
            }
        }
}

// ---------------------------------------------------------------------------
// Kernel 2: cv[bh] = tanh(t*wc[h]+bc[h]) @ v[bh].  2-stage pipeline (R7).
// ---------------------------------------------------------------------------
__global__ __launch_bounds__(256, 1) void cv_mma(
    const float* __restrict__ t_mat, const float* __restrict__ wc,
    const float* __restrict__ bc)
{
    extern __shared__ char smc[];
    const uint32_t sb = smem_u32(smc);
    const int tid = threadIdx.x, lane = tid & 31, wid = tid >> 5;
    const int hg = blockIdx.x, kt = blockIdx.y, b = blockIdx.z;
    const float wc0 = wc[hg * 2], bc0 = bc[hg * 2];
    const float wc1 = wc[hg * 2 + 1], bc1 = bc[hg * 2 + 1];
    const float* Tp = t_mat + (size_t)b * Sz * Sz + (size_t)(kt * 128) * Sz;
    const size_t vb0 = (size_t)(b * Hz + hg * 2) * Sz * Dz;
    const size_t vb1 = vb0 + (size_t)Sz * Dz;

    const int e = wid >> 2, rem = wid & 3;
    const int m0w = (rem >> 1) * 64, n0w = (rem & 1) * 32;

    const int aRow = tid >> 1, aHalf = tid & 1;
    const int bRow = tid >> 3, bSeg = tid & 7;

    float d[4][4][4] = {};

    auto stageA = [&](int s0, uint32_t base) {
        const float* tp = &Tp[(size_t)aRow * Sz + s0 + aHalf * 16];
        #pragma unroll
        for (int u = 0; u < 4; ++u) {
            float4 t4 = *(const float4*)&tp[u * 4];
            uint32_t off = (aRow * PA + aHalf * 16 + u * 4) * 2;
            uint32_t h0, l0, h1, l1;
            split_pack(tanh_fast(fmaf(t4.x, wc0, bc0)), tanh_fast(fmaf(t4.y, wc0, bc0)), h0, l0);
            split_pack(tanh_fast(fmaf(t4.z, wc0, bc0)), tanh_fast(fmaf(t4.w, wc0, bc0)), h1, l1);
            *(uint2*)(smc + (base + off)) = make_uint2(h0, h1);
            *(uint2*)(smc + (base + CV_APB + off)) = make_uint2(l0, l1);
            split_pack(tanh_fast(fmaf(t4.x, wc1, bc1)), tanh_fast(fmaf(t4.y, wc1, bc1)), h0, l0);
            split_pack(tanh_fast(fmaf(t4.z, wc1, bc1)), tanh_fast(fmaf(t4.w, wc1, bc1)), h1, l1);
            *(uint2*)(smc + (base + CV_ABLK + off)) = make_uint2(h0, h1);
            *(uint2*)(smc + (base + CV_ABLK + CV_APB + off)) = make_uint2(l0, l1);
        }
    };
    auto stageB = [&](int s0, uint32_t base) {
        size_t g0 = vb0 + (size_t)(s0 + bRow) * Dz + bSeg * 8;
        size_t g1 = vb1 + (size_t)(s0 + bRow) * Dz + bSeg * 8;
        uint32_t db = sb + base + CV_BOFF + (bRow * PV + bSeg * 8) * 2;
        cpa16(db, g_vh + g0);            cpa16(db + CV_BPB, g_vl + g0);
        cpa16(db + CV_BBLK, g_vh + g1);  cpa16(db + CV_BBLK + CV_BPB, g_vl + g1);
    };

    stageA(0, 0); stageB(0, 0);
    cpa_commit();
    for (int i = 0; i < 64; ++i) {
        const int p = i & 1;
        if (i + 1 < 64) {
            uint32_t nb = ((i + 1) & 1) * CV_STRIDE;
            stageA((i + 1) * 32, nb);
            stageB((i + 1) * 32, nb);
        }
        cpa_commit();
        cpa_wait1();
        __syncthreads();
        uint32_t base = sb + p * CV_STRIDE;
        uint32_t Ah = base + e * CV_ABLK;
        uint32_t Bh = base + CV_BOFF + e * CV_BBLK;
        mma_chunk(d, Ah, Ah + CV_APB, Bh, Bh + CV_BPB, PV, m0w, n0w, lane);
        __syncthreads();
    }

    float* Op = g_cv + (size_t)(b * Hz + hg * 2 + e) * Sz * Dz;
    #pragma unroll
    for (int mf = 0; mf < 4; ++mf)
        #pragma unroll
        for (int nf = 0; nf < 4; ++nf) {
            int row = kt * 128 + m0w + mf * 16 + (lane >> 2);
            int dd  = n0w + nf * 8 + ((lane & 3) << 1);
            *(float2*)&Op[(size_t)row * Dz + dd] = make_float2(d[mf][nf][0], d[mf][nf][1]);
            *(float2*)&Op[(size_t)(row + 8) * Dz + dd] = make_float2(d[mf][nf][2], d[mf][nf][3]);
        }
}

// ---------------------------------------------------------------------------
// Kernel 3: M[bh] = (1/sqrt(D)) * q[bh]^T @ cv[bh]  (64x64, K=2048), split-K x4
// ---------------------------------------------------------------------------
__global__ __launch_bounds__(256) void m_kernel()
{
    const int bh    = blockIdx.x;
    const int split = blockIdx.y;
    const float* Q   = g_q  + (size_t)bh * Sz * Dz;
    const float* CVp = g_cv + (size_t)bh * Sz * Dz;

    __shared__ float As[16][68];
    __shared__ float Bs[16][68];

    const int tid = threadIdx.x;
    const int tx = tid & 15;
    const int ty = tid >> 4;
    const int r  = tid >> 4;
    const int c4 = (tid & 15) * 4;

    float acc[4][4] = {};
    const int sBeg = split * (Sz / 4);

    for (int s0 = sBeg; s0 < sBeg + Sz / 4; s0 += 16) {
        *reinterpret_cast<float4*>(&As[r][c4]) =
            *reinterpret_cast<const float4*>(&Q[(size_t)(s0 + r) * Dz + c4]);
        *reinterpret_cast<float4*>(&Bs[r][c4]) =
            *reinterpret_cast<const float4*>(&CVp[(size_t)(s0 + r) * Dz + c4]);
        __syncthreads();
        #pragma unroll
        for (int kk = 0; kk < 16; ++kk) {
            float4 a = *reinterpret_cast<const float4*>(&As[kk][ty * 4]);
            float4 b = *reinterpret_cast<const float4*>(&Bs[kk][tx * 4]);
            float ar[4] = {a.x, a.y, a.z, a.w};
            float br[4] = {b.x, b.y, b.z, b.w};
            #pragma unroll
            for (int i = 0; i < 4; ++i)
                #pragma unroll
                for (int j = 0; j < 4; ++j)
                    acc[i][j] = fmaf(ar[i], br[j], acc[i][j]);
        }
        __syncthreads();
    }

    float* Mp = g_Mpart + ((size_t)split * BHz + bh) * Dz * Dz;
    #pragma unroll
    for (int i = 0; i < 4; ++i)
        #pragma unroll
        for (int j = 0; j < 4; ++j)
            Mp[(ty * 4 + i) * Dz + tx * 4 + j] = acc[i][j] * 0.125f;
}

// ---------------------------------------------------------------------------
// Kernel 4: Wk'[b][:, h*64+d] = wk[:, h*64+:] @ M[b,h]  (+ bias term bt)
// ---------------------------------------------------------------------------
__global__ __launch_bounds__(256) void wkm_kernel(
    const float* __restrict__ wk, const float* __restrict__ bk)
{
    const int bh = blockIdx.x;
    const int b  = bh >> 4;
    const int h  = bh & 15;
    const int c0 = blockIdx.y * 64;
    const int tid = threadIdx.x;

    __shared__ float Ms[Dz * Dz];
    __shared__ float Aw[Dz][68];

    {
        const float4* P0 = (const float4*)(g_Mpart + ((size_t)0 * BHz + bh) * Dz * Dz);
        const float4* P1 = (const float4*)(g_Mpart + ((size_t)1 * BHz + bh) * Dz * Dz);
        const float4* P2 = (const float4*)(g_Mpart + ((size_t)2 * BHz + bh) * Dz * Dz);
        const float4* P3 = (const float4*)(g_Mpart + ((size_t)3 * BHz + bh) * Dz * Dz);
        #pragma unroll
        for (int it = 0; it < 4; ++it) {
            int fi = it * 256 + tid;
            float4 a = P0[fi], bb = P1[fi], c = P2[fi], dd = P3[fi];
            float4 rr;
            rr.x = a.x + bb.x + c.x + dd.x;
            rr.y = a.y + bb.y + c.y + dd.y;
            rr.z = a.z + bb.z + c.z + dd.z;
            rr.w = a.w + bb.w + c.w + dd.w;
            ((float4*)Ms)[fi] = rr;
        }
    }
    {
        int cl = tid >> 2, dc = (tid & 3) * 16;
        #pragma unroll
        for (int j = 0; j < 4; ++j)
            *(float4*)&Aw[cl][dc + j * 4] =
                *(const float4*)&wk[(size_t)(c0 + cl) * Cz + h * 64 + dc + j * 4];
    }
    __syncthreads();

    const int ty = tid >> 4, tx = tid & 15;
    float acc[4][4] = {};
    #pragma unroll 8
    for (int kk = 0; kk < 64; ++kk) {
        float ar[4];
        #pragma unroll
        for (int i = 0; i < 4; ++i) ar[i] = Aw[ty * 4 + i][kk];
        float4 b4 = *(const float4*)&Ms[kk * Dz + tx * 4];
        float br[4] = {b4.x, b4.y, b4.z, b4.w};
        #pragma unroll
        for (int i = 0; i < 4; ++i)
            #pragma unroll
            for (int j = 0; j < 4; ++j)
                acc[i][j] = fmaf(ar[i], br[j], acc[i][j]);
    }

    u16* Wh = g_wkph + (size_t)b * Cz * Cz;
    u16* Wl = g_wkpl + (size_t)b * Cz * Cz;
    #pragma unroll
    for (int i = 0; i < 4; ++i) {
        size_t o = (size_t)(c0 + ty * 4 + i) * Cz + h * 64 + tx * 4;
        uint32_t hi, lo;
        split_pack(acc[i][0], acc[i][1], hi, lo);
        *(uint32_t*)&Wh[o] = hi; *(uint32_t*)&Wl[o] = lo;
        split_pack(acc[i][2], acc[i][3], hi, lo);
        *(uint32_t*)&Wh[o + 2] = hi; *(uint32_t*)&Wl[o + 2] = lo;
    }

    if (blockIdx.y == 0 && tid < 64) {
        float s = 0.f;
        #pragma unroll 8
        for (int dp = 0; dp < 64; ++dp)
            s = fmaf(bk[h * 64 + dp], Ms[dp * Dz + tid], s);
        g_bterm[b * Cz + h * 64 + tid] = s;
    }
}

// ---------------------------------------------------------------------------
// Kernel 5: c2[b][n] = sum_m bt[b][m] * wf[m][n]
// ---------------------------------------------------------------------------
__global__ __launch_bounds__(128) void c2_kernel(const float* __restrict__ wf)
{
    const int b = blockIdx.x;
    const int n = blockIdx.y * 128 + threadIdx.x;
    __shared__ float bt[Cz];
    for (int i = threadIdx.x; i < Cz; i += 128) bt[i] = g_bterm[b * Cz + i];
    __syncthreads();
    float acc = 0.f;
    #pragma unroll 8
    for (int m = 0; m < Cz; ++m)
        acc = fmaf(bt[m], wf[(size_t)m * Cz + n], acc);
    g_c2[b * Cz + n] = acc;
}

// ---------------------------------------------------------------------------
// Kernel 6: W2[b] = Wk'[b] @ wf  (bf16-split GEMM, output planes)
// ---------------------------------------------------------------------------
__global__ __launch_bounds__(256, 1) void w2_mma()
{
    extern __shared__ char smc[];
    const uint32_t sb = smem_u32(smc);
    const int tid = threadIdx.x, lane = tid & 31, wid = tid >> 5;
    const int wm = wid & 1, wn = wid >> 1;
    const int b = blockIdx.z;
    const int m0 = blockIdx.y * 128, n0 = blockIdx.x * 128;

    const u16* Ah = g_wkph + (size_t)b * Cz * Cz;
    const u16* Al = g_wkpl + (size_t)b * Cz * Cz;

    float d[4][4][4] = {};
    gemm_main(d, Ah, Al, g_wfh, g_wfl, sb, m0, n0, tid, lane, wm, wn, 32);

    u16* Wh = g_w2h + (size_t)b * Cz * Cz;
    u16* Wl = g_w2l + (size_t)b * Cz * Cz;
    #pragma unroll
    for (int mf = 0; mf < 4; ++mf)
        #pragma unroll
        for (int nf = 0; nf < 4; ++nf) {
            int mr = m0 + wm * 64 + mf * 16 + (lane >> 2);
            int nc = n0 + wn * 32 + nf * 8 + ((lane & 3) << 1);
            size_t i0 = (size_t)mr * Cz + nc;
            size_t i1 = i0 + (size_t)8 * Cz;
            uint32_t hi, lo;
            split_pack(d[mf][nf][0], d[mf][nf][1], hi, lo);
            *(uint32_t*)&Wh[i0] = hi; *(uint32_t*)&Wl[i0] = lo;
            split_pack(d[mf][nf][2], d[mf][nf][3], hi, lo);
            *(uint32_t*)&Wh[i1] = hi; *(uint32_t*)&Wl[i1] = lo;
        }
}

// ---------------------------------------------------------------------------
// Kernel 7: out = mish( x @ W2[b] + c2[b] + bf )
// ---------------------------------------------------------------------------
__global__ __launch_bounds__(256, 1) void final_mma(
    const float* __restrict__ bf, float* __restrict__ out)
{
    extern __shared__ char smc[];
    const uint32_t sb = smem_u32(smc);
    const int tid = threadIdx.x, lane = tid & 31, wid = tid >> 5;
    const int wm = wid & 1, wn = wid >> 1;
    const int m0 = blockIdx.y * 128, n0 = blockIdx.x * 128;
    const int b = m0 >> 11;

    const u16* Bh = g_w2h + (size_t)b * Cz * Cz;
    const u16* Bl = g_w2l + (size_t)b * Cz * Cz;

    float d[4][4][4] = {};
    gemm_main(d, g_xh, g_xl, Bh, Bl, sb, m0, n0, tid, lane, wm, wn, 32);

    #pragma unroll
    for (int mf = 0; mf < 4; ++mf)
        #pragma unroll
        for (int nf = 0; nf < 4; ++nf) {
            int mr = m0 + wm * 64 + mf * 16 + (lane >> 2);
            int nc = n0 + wn * 32 + nf * 8 + ((lane & 3) << 1);
            float bx = bf[nc] + g_c2[b * Cz + nc];
            float by = bf[nc + 1] + g_c2[b * Cz + nc + 1];
            *(float2*)&out[(size_t)mr * Cz + nc] =
                make_float2(mish_f(d[mf][nf][0] + bx), mish_f(d[mf][nf][1] + by));
            *(float2*)&out[(size_t)(mr + 8) * Cz + nc] =
                make_float2(mish_f(d[mf][nf][2] + bx), mish_f(d[mf][nf][3] + by));
        }
}

// ---------------------------------------------------------------------------
extern "C" void kernel_launch(void* const* d_in, const int* in_sizes, int n_in,
                              void* d_out, int out_size)
{
    const float* x  = (const float*)d_in[0];
    const float* y  = (const float*)d_in[1];
    const float* t  = (const float*)d_in[2];
    const float* bq = (const float*)d_in[4];
    const float* wk = (const float*)d_in[5];
    const float* bk = (const float*)d_in[6];
    const float* bv = (const float*)d_in[8];
    const float* wc = (const float*)d_in[9];
    const float* bc = (const float*)d_in[10];
    const float* wf = (const float*)d_in[11];
    const float* bf = (const float*)d_in[12];
    float* out = (float*)d_out;

    cudaFuncSetAttribute(proj_mma,  cudaFuncAttributeMaxDynamicSharedMemorySize, PROJ_SMEM);
    cudaFuncSetAttribute(cv_mma,    cudaFuncAttributeMaxDynamicSharedMemorySize, CV_SMEM);
    cudaFuncSetAttribute(w2_mma,    cudaFuncAttributeMaxDynamicSharedMemorySize, PROJ_SMEM);
    cudaFuncSetAttribute(final_mma, cudaFuncAttributeMaxDynamicSharedMemorySize, PROJ_SMEM);

    u16 *xh, *xl, *yh, *yl, *wqh, *wql, *wvh, *wvl, *wfh, *wfl;
    cudaGetSymbolAddress((void**)&xh,  g_xh);  cudaGetSymbolAddress((void**)&xl,  g_xl);
    cudaGetSymbolAddress((void**)&yh,  g_yh);  cudaGetSymbolAddress((void**)&yl,  g_yl);
    cudaGetSymbolAddress((void**)&wqh, g_wqh); cudaGetSymbolAddress((void**)&wql, g_wql);
    cudaGetSymbolAddress((void**)&wvh, g_wvh); cudaGetSymbolAddress((void**)&wvl, g_wvl);
    cudaGetSymbolAddress((void**)&wfh, g_wfh); cudaGetSymbolAddress((void**)&wfl, g_wfl);

    const int nAct = Bz * Sz * Cz;
    const int nW   = Cz * Cz;
    cvt_kernel<<<nAct / 1024, 256>>>(x, xh, xl, nAct);
    cvt_kernel<<<nAct / 1024, 256>>>(y, yh, yl, nAct);
    cvt_kernel<<<nW   / 1024, 256>>>((const float*)d_in[3],  wqh, wql, nW);
    cvt_kernel<<<nW   / 1024, 256>>>((const float*)d_in[7],  wvh, wvl, nW);
    cvt_kernel<<<nW   / 1024, 256>>>(wf, wfh, wfl, nW);

    // q,v projections (k projection folded away)
    proj_mma<<<dim3(Cz / 128, (Bz * Sz) / 128, 2), 256, PROJ_SMEM>>>(bq, bv);
    // cv = tanh(t*wc+bc) @ v
    cv_mma<<<dim3(Hz / 2, Sz / 128, Bz), 256, CV_SMEM>>>(t, wc, bc);
    // M = q^T @ cv / sqrt(D), split-K x4
    m_kernel<<<dim3(BHz, 4), 256>>>();
    // Wk' = wk @ M (+ bias term)
    wkm_kernel<<<dim3(BHz, 16), 256>>>(wk, bk);
    // c2 = bt @ wf
    c2_kernel<<<dim3(Bz, 8), 128>>>(wf);
    // W2 = Wk' @ wf
    w2_mma<<<dim3(Cz / 128, Cz / 128, Bz), 256, PROJ_SMEM>>>();
    // out = mish(x @ W2 + c2 + bf)
    final_mma<<<dim3(Cz / 128, (Bz * Sz) / 128), 256, PROJ_SMEM>>>(bf, out);
}

// round 12
// speedup vs baseline: 1.1027x; 1.1027x over previous
#include <cuda_runtime.h>
#include <cuda_bf16.h>
#include <math.h>
#include <stdint.h>

#define Bz 2
#define Sz 2048
#define Cz 1024
#define Hz 16
#define Dz 64
#define BHz 32

typedef unsigned short u16;

// ---------------------------------------------------------------------------
// Scratch (device globals)
// ---------------------------------------------------------------------------
__device__ float g_q[BHz * Sz * Dz];
__device__ float g_k[BHz * Sz * Dz];
__device__ float g_cv[BHz * Sz * Dz];
__device__ float g_Mpart[4 * BHz * Dz * Dz];

// bf16 hi/lo planes
__device__ u16 g_xh[Bz * Sz * Cz], g_xl[Bz * Sz * Cz];
__device__ u16 g_yh[Bz * Sz * Cz], g_yl[Bz * Sz * Cz];
__device__ u16 g_wqh[Cz * Cz], g_wql[Cz * Cz];
__device__ u16 g_wkh[Cz * Cz], g_wkl[Cz * Cz];
__device__ u16 g_wvh[Cz * Cz], g_wvl[Cz * Cz];
__device__ u16 g_wfh[Cz * Cz], g_wfl[Cz * Cz];
__device__ u16 g_vh[BHz * Sz * Dz], g_vl[BHz * Sz * Dz];
__device__ u16 g_mh[Bz * Sz * Cz], g_ml[Bz * Sz * Cz];

// ---------------------------------------------------------------------------
// Helpers
// ---------------------------------------------------------------------------
__device__ __forceinline__ uint32_t smem_u32(const void* p) {
    return (uint32_t)__cvta_generic_to_shared(p);
}
__device__ __forceinline__ void ldsm4(uint32_t* r, uint32_t a) {
    asm volatile("ldmatrix.sync.aligned.m8n8.x4.shared.b16 {%0,%1,%2,%3},[%4];"
                 : "=r"(r[0]), "=r"(r[1]), "=r"(r[2]), "=r"(r[3]) : "r"(a));
}
__device__ __forceinline__ void ldsm4t(uint32_t* r, uint32_t a) {
    asm volatile("ldmatrix.sync.aligned.m8n8.x4.trans.shared.b16 {%0,%1,%2,%3},[%4];"
                 : "=r"(r[0]), "=r"(r[1]), "=r"(r[2]), "=r"(r[3]) : "r"(a));
}
__device__ __forceinline__ void mma16816(float* d, const uint32_t* a, const uint32_t* b) {
    asm volatile("mma.sync.aligned.m16n8k16.row.col.f32.bf16.bf16.f32 "
                 "{%0,%1,%2,%3},{%4,%5,%6,%7},{%8,%9},{%0,%1,%2,%3};"
                 : "+f"(d[0]), "+f"(d[1]), "+f"(d[2]), "+f"(d[3])
                 : "r"(a[0]), "r"(a[1]), "r"(a[2]), "r"(a[3]), "r"(b[0]), "r"(b[1]));
}
__device__ __forceinline__ void cpa16(uint32_t s, const void* g) {
    asm volatile("cp.async.cg.shared.global [%0], [%1], 16;" :: "r"(s), "l"(g));
}
__device__ __forceinline__ void cpa_commit() {
    asm volatile("cp.async.commit_group;" ::: "memory");
}
__device__ __forceinline__ void cpa_wait1() {
    asm volatile("cp.async.wait_group 1;" ::: "memory");
}
__device__ __forceinline__ void split_pack(float x, float y, uint32_t& hi, uint32_t& lo) {
    __nv_bfloat16 hx = __float2bfloat16_rn(x), hy = __float2bfloat16_rn(y);
    __nv_bfloat16 lx = __float2bfloat16_rn(x - __bfloat162float(hx));
    __nv_bfloat16 ly = __float2bfloat16_rn(y - __bfloat162float(hy));
    hi = ((uint32_t)__bfloat16_as_ushort(hy) << 16) | (uint32_t)__bfloat16_as_ushort(hx);
    lo = ((uint32_t)__bfloat16_as_ushort(ly) << 16) | (uint32_t)__bfloat16_as_ushort(lx);
}
__device__ __forceinline__ float tanh_fast(float x) {
    float xc = fminf(fmaxf(x, -12.0f), 12.0f);
    float e = __expf(2.0f * xc);
    return __fdividef(e - 1.0f, e + 1.0f);
}
__device__ __forceinline__ float mish_f(float v) {
    float sp = (v > 20.0f) ? v : log1pf(expf(v));
    return v * tanhf(sp);
}

// ---------------------------------------------------------------------------
// Kernel 0a: activations fp32 -> bf16 hi/lo (z selects x or y)
// ---------------------------------------------------------------------------
__global__ __launch_bounds__(256) void cvt_act(
    const float* __restrict__ x, const float* __restrict__ y)
{
    const int n = Bz * Sz * Cz;
    int i = (blockIdx.x * 256 + threadIdx.x) * 4;
    const float* src = blockIdx.y ? y : x;
    u16* ph = blockIdx.y ? g_yh : g_xh;
    u16* pl = blockIdx.y ? g_yl : g_xl;
    if (i < n) {
        float4 v = *(const float4*)&src[i];
        uint32_t h0, l0, h1, l1;
        split_pack(v.x, v.y, h0, l0);
        split_pack(v.z, v.w, h1, l1);
        *(uint2*)&ph[i] = make_uint2(h0, h1);
        *(uint2*)&pl[i] = make_uint2(l0, l1);
    }
}

// Kernel 0b: weights fp32 -> bf16 hi/lo (z selects wq/wk/wv/wf)
__global__ __launch_bounds__(256) void cvt_w(
    const float* __restrict__ wq, const float* __restrict__ wk,
    const float* __restrict__ wv, const float* __restrict__ wf)
{
    const int n = Cz * Cz;
    int i = (blockIdx.x * 256 + threadIdx.x) * 4;
    const float* src; u16* ph; u16* pl;
    switch (blockIdx.y) {
        case 0: src = wq; ph = g_wqh; pl = g_wql; break;
        case 1: src = wk; ph = g_wkh; pl = g_wkl; break;
        case 2: src = wv; ph = g_wvh; pl = g_wvl; break;
        default: src = wf; ph = g_wfh; pl = g_wfl; break;
    }
    if (i < n) {
        float4 v = *(const float4*)&src[i];
        uint32_t h0, l0, h1, l1;
        split_pack(v.x, v.y, h0, l0);
        split_pack(v.z, v.w, h1, l1);
        *(uint2*)&ph[i] = make_uint2(h0, h1);
        *(uint2*)&pl[i] = make_uint2(l0, l1);
    }
}

// ---------------------------------------------------------------------------
// Shared-memory geometry
// ---------------------------------------------------------------------------
#define PA 40     // A tile pitch (32 + 8 pad), bf16 elems
#define PB 136    // B tile pitch (128 + 8 pad)
#define PV 72     // v tile pitch (64 + 8 pad)

#define PRJ_APB   10240                 // one A plane: 128*40*2
#define PRJ_BOFF  20480
#define PRJ_BPB   8704                  // one B plane: 32*136*2
#define PRJ_STRIDE 37888
#define PROJ_SMEM (2 * PRJ_STRIDE)      // 74 KB -> 2 CTAs/SM possible

#define CV_APB   10240
#define CV_ABLK  20480
#define CV_BOFF  40960
#define CV_BPB   4608
#define CV_BBLK  9216
#define CV_STRIDE 59392
#define CV_SMEM  (2 * CV_STRIDE)

// stage one (A 128x32, B 32x128) chunk pair of hi/lo planes via cp.async
__device__ __forceinline__ void stage_prj(
    const u16* __restrict__ Ah, const u16* __restrict__ Al,
    const u16* __restrict__ Bh, const u16* __restrict__ Bl,
    uint32_t base, int m0, int n0, int k0, int tid)
{
    int row = tid >> 1, half = tid & 1;
    size_t ga = (size_t)(m0 + row) * Cz + k0 + half * 16;
    uint32_t da = base + (row * PA + half * 16) * 2;
    cpa16(da, Ah + ga);               cpa16(da + 16, Ah + ga + 8);
    cpa16(da + PRJ_APB, Al + ga);     cpa16(da + PRJ_APB + 16, Al + ga + 8);
    int br = tid >> 3, seg = tid & 7;
    size_t gb = (size_t)(k0 + br) * Cz + n0 + seg * 8;
    uint32_t db = base + PRJ_BOFF + (br * PB + seg * 8) * 2;
    cpa16(db, Bh + gb);               cpa16(db + 128, Bh + gb + 64);
    cpa16(db + PRJ_BPB, Bl + gb);     cpa16(db + PRJ_BPB + 128, Bl + gb + 64);
}

// one 32-k chunk of 3-term split MMAs (warp tile 64x32, frags 4x4)
__device__ __forceinline__ void mma_chunk(
    float d[4][4][4], uint32_t Ah, uint32_t Al, uint32_t Bh, uint32_t Bl,
    int pitchB, int wm64, int wn32, int lane)
{
    #pragma unroll
    for (int k16 = 0; k16 < 32; k16 += 16) {
        uint32_t ah[4][4], al[4][4];
        #pragma unroll
        for (int mf = 0; mf < 4; ++mf) {
            int mr = wm64 + mf * 16 + (lane & 15);
            int kc = k16 + ((lane >> 4) << 3);
            ldsm4(ah[mf], Ah + (mr * PA + kc) * 2);
            ldsm4(al[mf], Al + (mr * PA + kc) * 2);
        }
        uint32_t bh[4][2], bl[4][2];
        #pragma unroll
        for (int nf2 = 0; nf2 < 2; ++nf2) {
            int kr = k16 + (lane & 7) + ((lane >> 3) & 1) * 8;
            int nc = wn32 + nf2 * 16 + ((lane >> 4) << 3);
            uint32_t t[4];
            ldsm4t(t, Bh + (kr * pitchB + nc) * 2);
            bh[nf2 * 2][0] = t[0]; bh[nf2 * 2][1] = t[1];
            bh[nf2 * 2 + 1][0] = t[2]; bh[nf2 * 2 + 1][1] = t[3];
            ldsm4t(t, Bl + (kr * pitchB + nc) * 2);
            bl[nf2 * 2][0] = t[0]; bl[nf2 * 2][1] = t[1];
            bl[nf2 * 2 + 1][0] = t[2]; bl[nf2 * 2 + 1][1] = t[3];
        }
        #pragma unroll
        for (int mf = 0; mf < 4; ++mf)
            #pragma unroll
            for (int nf = 0; nf < 4; ++nf) {
                mma16816(d[mf][nf], ah[mf], bh[nf]);
                mma16816(d[mf][nf], ah[mf], bl[nf]);
                mma16816(d[mf][nf], al[mf], bh[nf]);
            }
    }
}

// 2-stage double-buffered mainloop (R7 known-good): K = kiters*32
__device__ __forceinline__ void gemm_main(
    float d[4][4][4], const u16* Ah, const u16* Al,
    const u16* Bh, const u16* Bl,
    uint32_t sb, int m0, int n0, int tid, int lane, int wm, int wn, int kiters)
{
    stage_prj(Ah, Al, Bh, Bl, sb, m0, n0, 0, tid);
    cpa_commit();
    for (int i = 0; i < kiters; ++i) {
        const int p = i & 1;
        if (i + 1 < kiters)
            stage_prj(Ah, Al, Bh, Bl, sb + ((i + 1) & 1) * PRJ_STRIDE,
                      m0, n0, (i + 1) * 32, tid);
        cpa_commit();
        cpa_wait1();
        __syncthreads();
        uint32_t base = sb + p * PRJ_STRIDE;
        mma_chunk(d, base, base + PRJ_APB, base + PRJ_BOFF, base + PRJ_BOFF + PRJ_BPB,
                  PB, wm * 64, wn * 32, lane);
        __syncthreads();
    }
}

// ---------------------------------------------------------------------------
// Kernel 1: q/k/v projections. which: 0=q(y,wq) 1=k(x,wk) 2=v(y,wv)
// q,k written fp32 split-head; v written as bf16 hi/lo planes.
// __launch_bounds__(256,2): allow 2 CTAs/SM (74KB smem x2 fits 228KB).
// ---------------------------------------------------------------------------
__global__ __launch_bounds__(256, 2) void proj_mma(
    const float* __restrict__ bq, const float* __restrict__ bk,
    const float* __restrict__ bv)
{
    extern __shared__ char smc[];
    const uint32_t sb = smem_u32(smc);
    const int tid = threadIdx.x, lane = tid & 31, wid = tid >> 5;
    const int wm = wid & 1, wn = wid >> 1;
    const int which = blockIdx.z;
    const u16* Ahg = (which == 1) ? g_xh : g_yh;
    const u16* Alg = (which == 1) ? g_xl : g_yl;
    const u16* Bhg = (which == 0) ? g_wqh : (which == 1) ? g_wkh : g_wvh;
    const u16* Blg = (which == 0) ? g_wql : (which == 1) ? g_wkl : g_wvl;
    const float* bias = (which == 0) ? bq : (which == 1) ? bk : bv;
    const int m0 = blockIdx.y * 128, n0 = blockIdx.x * 128;

    float d[4][4][4] = {};
    gemm_main(d, Ahg, Alg, Bhg, Blg, sb, m0, n0, tid, lane, wm, wn, 32);

    #pragma unroll
    for (int mf = 0; mf < 4; ++mf)
        #pragma unroll
        for (int nf = 0; nf < 4; ++nf) {
            int mr = m0 + wm * 64 + mf * 16 + (lane >> 2);
            int nc = n0 + wn * 32 + nf * 8 + ((lane & 3) << 1);
            float2 bv2 = *(const float2*)&bias[nc];
            int bb = mr >> 11, s = mr & (Sz - 1);
            int h = nc >> 6, dd = nc & 63;
            size_t i0 = (((size_t)bb * Hz + h) * Sz + s) * Dz + dd;
            size_t i1 = (((size_t)bb * Hz + h) * Sz + s + 8) * Dz + dd;
            if (which == 2) {
                uint32_t hi, lo;
                split_pack(d[mf][nf][0] + bv2.x, d[mf][nf][1] + bv2.y, hi, lo);
                *(uint32_t*)&g_vh[i0] = hi; *(uint32_t*)&g_vl[i0] = lo;
                split_pack(d[mf][nf][2] + bv2.x, d[mf][nf][3] + bv2.y, hi, lo);
                *(uint32_t*)&g_vh[i1] = hi; *(uint32_t*)&g_vl[i1] = lo;
            } else {
                float* out = (which == 0) ? g_q : g_k;
                *(float2*)&out[i0] = make_float2(d[mf][nf][0] + bv2.x, d[mf][nf][1] + bv2.y);
                *(float2*)&out[i1] = make_float2(d[mf][nf][2] + bv2.x, d[mf][nf][3] + bv2.y);
            }
        }
}

// ---------------------------------------------------------------------------
// Kernel 2: cv[bh] = tanh(t*wc[h]+bc[h]) @ v[bh].  2-stage pipeline (R7).
// ---------------------------------------------------------------------------
__global__ __launch_bounds__(256, 1) void cv_mma(
    const float* __restrict__ t_mat, const float* __restrict__ wc,
    const float* __restrict__ bc)
{
    extern __shared__ char smc[];
    const uint32_t sb = smem_u32(smc);
    const int tid = threadIdx.x, lane = tid & 31, wid = tid >> 5;
    const int hg = blockIdx.x, kt = blockIdx.y, b = blockIdx.z;
    const float wc0 = wc[hg * 2], bc0 = bc[hg * 2];
    const float wc1 = wc[hg * 2 + 1], bc1 = bc[hg * 2 + 1];
    const float* Tp = t_mat + (size_t)b * Sz * Sz + (size_t)(kt * 128) * Sz;
    const size_t vb0 = (size_t)(b * Hz + hg * 2) * Sz * Dz;
    const size_t vb1 = vb0 + (size_t)Sz * Dz;

    const int e = wid >> 2, rem = wid & 3;
    const int m0w = (rem >> 1) * 64, n0w = (rem & 1) * 32;

    const int aRow = tid >> 1, aHalf = tid & 1;
    const int bRow = tid >> 3, bSeg = tid & 7;

    float d[4][4][4] = {};

    auto stageA = [&](int s0, uint32_t base) {
        const float* tp = &Tp[(size_t)aRow * Sz + s0 + aHalf * 16];
        #pragma unroll
        for (int u = 0; u < 4; ++u) {
            float4 t4 = *(const float4*)&tp[u * 4];
            uint32_t off = (aRow * PA + aHalf * 16 + u * 4) * 2;
            uint32_t h0, l0, h1, l1;
            split_pack(tanh_fast(fmaf(t4.x, wc0, bc0)), tanh_fast(fmaf(t4.y, wc0, bc0)), h0, l0);
            split_pack(tanh_fast(fmaf(t4.z, wc0, bc0)), tanh_fast(fmaf(t4.w, wc0, bc0)), h1, l1);
            *(uint2*)(smc + (base + off)) = make_uint2(h0, h1);
            *(uint2*)(smc + (base + CV_APB + off)) = make_uint2(l0, l1);
            split_pack(tanh_fast(fmaf(t4.x, wc1, bc1)), tanh_fast(fmaf(t4.y, wc1, bc1)), h0, l0);
            split_pack(tanh_fast(fmaf(t4.z, wc1, bc1)), tanh_fast(fmaf(t4.w, wc1, bc1)), h1, l1);
            *(uint2*)(smc + (base + CV_ABLK + off)) = make_uint2(h0, h1);
            *(uint2*)(smc + (base + CV_ABLK + CV_APB + off)) = make_uint2(l0, l1);
        }
    };
    auto stageB = [&](int s0, uint32_t base) {
        size_t g0 = vb0 + (size_t)(s0 + bRow) * Dz + bSeg * 8;
        size_t g1 = vb1 + (size_t)(s0 + bRow) * Dz + bSeg * 8;
        uint32_t db = sb + base + CV_BOFF + (bRow * PV + bSeg * 8) * 2;
        cpa16(db, g_vh + g0);            cpa16(db + CV_BPB, g_vl + g0);
        cpa16(db + CV_BBLK, g_vh + g1);  cpa16(db + CV_BBLK + CV_BPB, g_vl + g1);
    };

    stageA(0, 0); stageB(0, 0);
    cpa_commit();
    for (int i = 0; i < 64; ++i) {
        const int p = i & 1;
        if (i + 1 < 64) {
            uint32_t nb = ((i + 1) & 1) * CV_STRIDE;
            stageA((i + 1) * 32, nb);
            stageB((i + 1) * 32, nb);
        }
        cpa_commit();
        cpa_wait1();
        __syncthreads();
        uint32_t base = sb + p * CV_STRIDE;
        uint32_t Ah = base + e * CV_ABLK;
        uint32_t Bh = base + CV_BOFF + e * CV_BBLK;
        mma_chunk(d, Ah, Ah + CV_APB, Bh, Bh + CV_BPB, PV, m0w, n0w, lane);
        __syncthreads();
    }

    float* Op = g_cv + (size_t)(b * Hz + hg * 2 + e) * Sz * Dz;
    #pragma unroll
    for (int mf = 0; mf < 4; ++mf)
        #pragma unroll
        for (int nf = 0; nf < 4; ++nf) {
            int row = kt * 128 + m0w + mf * 16 + (lane >> 2);
            int dd  = n0w + nf * 8 + ((lane & 3) << 1);
            *(float2*)&Op[(size_t)row * Dz + dd] = make_float2(d[mf][nf][0], d[mf][nf][1]);
            *(float2*)&Op[(size_t)(row + 8) * Dz + dd] = make_float2(d[mf][nf][2], d[mf][nf][3]);
        }
}

// ---------------------------------------------------------------------------
// Kernel 3: M[bh] = (1/sqrt(D)) * q[bh]^T @ cv[bh]  (64x64, K=2048), split-K x4
// ---------------------------------------------------------------------------
__global__ __launch_bounds__(256) void m_kernel()
{
    const int bh    = blockIdx.x;
    const int split = blockIdx.y;
    const float* Q   = g_q  + (size_t)bh * Sz * Dz;
    const float* CVp = g_cv + (size_t)bh * Sz * Dz;

    __shared__ float As[16][68];
    __shared__ float Bs[16][68];

    const int tid = threadIdx.x;
    const int tx = tid & 15;
    const int ty = tid >> 4;
    const int r  = tid >> 4;
    const int c4 = (tid & 15) * 4;

    float acc[4][4] = {};
    const int sBeg = split * (Sz / 4);

    for (int s0 = sBeg; s0 < sBeg + Sz / 4; s0 += 16) {
        *reinterpret_cast<float4*>(&As[r][c4]) =
            *reinterpret_cast<const float4*>(&Q[(size_t)(s0 + r) * Dz + c4]);
        *reinterpret_cast<float4*>(&Bs[r][c4]) =
            *reinterpret_cast<const float4*>(&CVp[(size_t)(s0 + r) * Dz + c4]);
        __syncthreads();
        #pragma unroll
        for (int kk = 0; kk < 16; ++kk) {
            float4 a = *reinterpret_cast<const float4*>(&As[kk][ty * 4]);
            float4 b = *reinterpret_cast<const float4*>(&Bs[kk][tx * 4]);
            float ar[4] = {a.x, a.y, a.z, a.w};
            float br[4] = {b.x, b.y, b.z, b.w};
            #pragma unroll
            for (int i = 0; i < 4; ++i)
                #pragma unroll
                for (int j = 0; j < 4; ++j)
                    acc[i][j] = fmaf(ar[i], br[j], acc[i][j]);
        }
        __syncthreads();
    }

    float* Mp = g_Mpart + ((size_t)split * BHz + bh) * Dz * Dz;
    #pragma unroll
    for (int i = 0; i < 4; ++i)
        #pragma unroll
        for (int j = 0; j < 4; ++j)
            Mp[(ty * 4 + i) * Dz + tx * 4 + j] = acc[i][j] * 0.125f;
}

// ---------------------------------------------------------------------------
// Kernel 4: att[bh] = k[bh] @ M[bh] -> merged written as bf16 hi/lo planes
// ---------------------------------------------------------------------------
__global__ __launch_bounds__(256) void att_kernel()
{
    const int bh = blockIdx.z;
    const int b  = bh >> 4;
    const int h  = bh & 15;
    const int s0 = blockIdx.y * 64;
    const float* Kp = g_k + (size_t)bh * Sz * Dz;

    __shared__ float Ms[Dz * Dz];
    __shared__ float As[16][68];

    const int tid = threadIdx.x;
    const int tx = tid & 15;
    const int ty = tid >> 4;

    const float4* P0 = reinterpret_cast<const float4*>(g_Mpart + ((size_t)0 * BHz + bh) * Dz * Dz);
    const float4* P1 = reinterpret_cast<const float4*>(g_Mpart + ((size_t)1 * BHz + bh) * Dz * Dz);
    const float4* P2 = reinterpret_cast<const float4*>(g_Mpart + ((size_t)2 * BHz + bh) * Dz * Dz);
    const float4* P3 = reinterpret_cast<const float4*>(g_Mpart + ((size_t)3 * BHz + bh) * Dz * Dz);
    #pragma unroll
    for (int it = 0; it < 4; ++it) {
        int fi = it * 256 + tid;
        float4 a = P0[fi], bb4 = P1[fi], c = P2[fi], dd = P3[fi];
        float4 rr;
        rr.x = a.x + bb4.x + c.x + dd.x;
        rr.y = a.y + bb4.y + c.y + dd.y;
        rr.z = a.z + bb4.z + c.z + dd.z;
        rr.w = a.w + bb4.w + c.w + dd.w;
        reinterpret_cast<float4*>(Ms)[fi] = rr;
    }
    __syncthreads();

    const int aRow = tid >> 2;
    const int aCol = (tid & 3) * 4;

    float acc[4][4] = {};
    #pragma unroll
    for (int kb = 0; kb < 4; ++kb) {
        float4 a4 = *reinterpret_cast<const float4*>(&Kp[(size_t)(s0 + aRow) * Dz + kb * 16 + aCol]);
        As[aCol + 0][aRow] = a4.x;
        As[aCol + 1][aRow] = a4.y;
        As[aCol + 2][aRow] = a4.z;
        As[aCol + 3][aRow] = a4.w;
        __syncthreads();
        #pragma unroll
        for (int kk = 0; kk < 16; ++kk) {
            float4 a = *reinterpret_cast<const float4*>(&As[kk][ty * 4]);
            float4 bm = *reinterpret_cast<const float4*>(&Ms[(kb * 16 + kk) * Dz + tx * 4]);
            float ar[4] = {a.x, a.y, a.z, a.w};
            float br[4] = {bm.x, bm.y, bm.z, bm.w};
            #pragma unroll
            for (int i = 0; i < 4; ++i)
                #pragma unroll
                for (int j = 0; j < 4; ++j)
                    acc[i][j] = fmaf(ar[i], br[j], acc[i][j]);
        }
        __syncthreads();
    }

    #pragma unroll
    for (int i = 0; i < 4; ++i) {
        size_t rowi = ((size_t)b * Sz + s0 + ty * 4 + i) * Cz + h * Dz + tx * 4;
        uint32_t hi, lo;
        split_pack(acc[i][0], acc[i][1], hi, lo);
        *(uint32_t*)&g_mh[rowi] = hi; *(uint32_t*)&g_ml[rowi] = lo;
        split_pack(acc[i][2], acc[i][3], hi, lo);
        *(uint32_t*)&g_mh[rowi + 2] = hi; *(uint32_t*)&g_ml[rowi + 2] = lo;
    }
}

// ---------------------------------------------------------------------------
// Kernel 5: out = mish(merged @ wf + bf).  occ-2 like proj.
// ---------------------------------------------------------------------------
__global__ __launch_bounds__(256, 2) void final_mma(
    const float* __restrict__ bf, float* __restrict__ out)
{
    extern __shared__ char smc[];
    const uint32_t sb = smem_u32(smc);
    const int tid = threadIdx.x, lane = tid & 31, wid = tid >> 5;
    const int wm = wid & 1, wn = wid >> 1;
    const int m0 = blockIdx.y * 128, n0 = blockIdx.x * 128;

    float d[4][4][4] = {};
    gemm_main(d, g_mh, g_ml, g_wfh, g_wfl, sb, m0, n0, tid, lane, wm, wn, 32);

    #pragma unroll
    for (int mf = 0; mf < 4; ++mf)
        #pragma unroll
        for (int nf = 0; nf < 4; ++nf) {
            int mr = m0 + wm * 64 + mf * 16 + (lane >> 2);
            int nc = n0 + wn * 32 + nf * 8 + ((lane & 3) << 1);
            float2 bv2 = *(const float2*)&bf[nc];
            *(float2*)&out[(size_t)mr * Cz + nc] =
                make_float2(mish_f(d[mf][nf][0] + bv2.x), mish_f(d[mf][nf][1] + bv2.y));
            *(float2*)&out[(size_t)(mr + 8) * Cz + nc] =
                make_float2(mish_f(d[mf][nf][2] + bv2.x), mish_f(d[mf][nf][3] + bv2.y));
        }
}

// ---------------------------------------------------------------------------
extern "C" void kernel_launch(void* const* d_in, const int* in_sizes, int n_in,
                              void* d_out, int out_size)
{
    const float* x  = (const float*)d_in[0];
    const float* y  = (const float*)d_in[1];
    const float* t  = (const float*)d_in[2];
    const float* wq = (const float*)d_in[3];
    const float* bq = (const float*)d_in[4];
    const float* wk = (const float*)d_in[5];
    const float* bk = (const float*)d_in[6];
    const float* wv = (const float*)d_in[7];
    const float* bv = (const float*)d_in[8];
    const float* wc = (const float*)d_in[9];
    const float* bc = (const float*)d_in[10];
    const float* wf = (const float*)d_in[11];
    const float* bf = (const float*)d_in[12];
    float* out = (float*)d_out;

    cudaFuncSetAttribute(proj_mma,  cudaFuncAttributeMaxDynamicSharedMemorySize, PROJ_SMEM);
    cudaFuncSetAttribute(cv_mma,    cudaFuncAttributeMaxDynamicSharedMemorySize, CV_SMEM);
    cudaFuncSetAttribute(final_mma, cudaFuncAttributeMaxDynamicSharedMemorySize, PROJ_SMEM);

    const int nAct = Bz * Sz * Cz;
    const int nW   = Cz * Cz;
    // conversions: activations (x,y) and weights (wq,wk,wv,wf), z-indexed
    cvt_act<<<dim3(nAct / 1024, 2), 256>>>(x, y);
    cvt_w<<<dim3(nW / 1024, 4), 256>>>(wq, wk, wv, wf);

    // q,k,v projections
    proj_mma<<<dim3(Cz / 128, (Bz * Sz) / 128, 3), 256, PROJ_SMEM>>>(bq, bk, bv);
    // cv = tanh(t*wc+bc) @ v  (c never materialized)
    cv_mma<<<dim3(Hz / 2, Sz / 128, Bz), 256, CV_SMEM>>>(t, wc, bc);
    // M = q^T @ cv / sqrt(D), split-K x4
    m_kernel<<<dim3(BHz, 4), 256>>>();
    // att = k @ M -> merged bf16 planes
    att_kernel<<<dim3(1, Sz / 64, BHz), 256>>>();
    // out = mish(merged @ wf + bf)
    final_mma<<<dim3(Cz / 128, (Bz * Sz) / 128), 256, PROJ_SMEM>>>(bf, out);
}

// round 16
// speedup vs baseline: 1.1612x; 1.0530x over previous
#include <cuda_runtime.h>
#include <cuda_bf16.h>
#include <math.h>
#include <stdint.h>

#define Bz 2
#define Sz 2048
#define Cz 1024
#define Hz 16
#define Dz 64
#define BHz 32

typedef unsigned short u16;

// ---------------------------------------------------------------------------
// Scratch (device globals)
// ---------------------------------------------------------------------------
__device__ float g_q[BHz * Sz * Dz];
__device__ float g_k[BHz * Sz * Dz];
__device__ float g_cv[BHz * Sz * Dz];
__device__ float g_Mpart[4 * BHz * Dz * Dz];

// bf16 hi/lo planes
__device__ u16 g_xh[Bz * Sz * Cz], g_xl[Bz * Sz * Cz];
__device__ u16 g_yh[Bz * Sz * Cz], g_yl[Bz * Sz * Cz];
__device__ u16 g_wqh[Cz * Cz], g_wql[Cz * Cz];
__device__ u16 g_wkh[Cz * Cz], g_wkl[Cz * Cz];
__device__ u16 g_wvh[Cz * Cz], g_wvl[Cz * Cz];
__device__ u16 g_wfh[Cz * Cz], g_wfl[Cz * Cz];
__device__ u16 g_vh[BHz * Sz * Dz], g_vl[BHz * Sz * Dz];
__device__ u16 g_mh[Bz * Sz * Cz], g_ml[Bz * Sz * Cz];

// ---------------------------------------------------------------------------
// Helpers
// ---------------------------------------------------------------------------
__device__ __forceinline__ uint32_t smem_u32(const void* p) {
    return (uint32_t)__cvta_generic_to_shared(p);
}
__device__ __forceinline__ void ldsm4(uint32_t* r, uint32_t a) {
    asm volatile("ldmatrix.sync.aligned.m8n8.x4.shared.b16 {%0,%1,%2,%3},[%4];"
                 : "=r"(r[0]), "=r"(r[1]), "=r"(r[2]), "=r"(r[3]) : "r"(a));
}
__device__ __forceinline__ void ldsm4t(uint32_t* r, uint32_t a) {
    asm volatile("ldmatrix.sync.aligned.m8n8.x4.trans.shared.b16 {%0,%1,%2,%3},[%4];"
                 : "=r"(r[0]), "=r"(r[1]), "=r"(r[2]), "=r"(r[3]) : "r"(a));
}
__device__ __forceinline__ void mma16816(float* d, const uint32_t* a, const uint32_t* b) {
    asm volatile("mma.sync.aligned.m16n8k16.row.col.f32.bf16.bf16.f32 "
                 "{%0,%1,%2,%3},{%4,%5,%6,%7},{%8,%9},{%0,%1,%2,%3};"
                 : "+f"(d[0]), "+f"(d[1]), "+f"(d[2]), "+f"(d[3])
                 : "r"(a[0]), "r"(a[1]), "r"(a[2]), "r"(a[3]), "r"(b[0]), "r"(b[1]));
}
__device__ __forceinline__ void cpa16(uint32_t s, const void* g) {
    asm volatile("cp.async.cg.shared.global [%0], [%1], 16;" :: "r"(s), "l"(g));
}
__device__ __forceinline__ void cpa_commit() {
    asm volatile("cp.async.commit_group;" ::: "memory");
}
__device__ __forceinline__ void cpa_wait1() {
    asm volatile("cp.async.wait_group 1;" ::: "memory");
}
// fast fp32 pair -> (hi,lo) bf16x2 split using cvt.rn.bf16x2 (3 ops/elem)
__device__ __forceinline__ void split_pack(float x, float y, uint32_t& hi, uint32_t& lo) {
    uint32_t h;
    asm("cvt.rn.bf16x2.f32 %0, %1, %2;" : "=r"(h) : "f"(y), "f"(x));
    float hx = __uint_as_float(h << 16);
    float hy = __uint_as_float(h & 0xffff0000u);
    float lx = x - hx, ly = y - hy;
    asm("cvt.rn.bf16x2.f32 %0, %1, %2;" : "=r"(lo) : "f"(ly), "f"(lx));
    hi = h;
}
// tanh(x) = 1 - 2/(1+e^{2x}); clamp-free (correct +-1 limits at overflow)
__device__ __forceinline__ float tanh_fast(float x) {
    float e = __expf(2.0f * x);
    return fmaf(-2.0f, __fdividef(1.0f, e + 1.0f), 1.0f);
}
__device__ __forceinline__ float mish_f(float v) {
    float sp = (v > 20.0f) ? v : log1pf(expf(v));
    return v * tanhf(sp);
}

// ---------------------------------------------------------------------------
// Kernel 0a: activations fp32 -> bf16 hi/lo (z selects x or y)
// ---------------------------------------------------------------------------
__global__ __launch_bounds__(256) void cvt_act(
    const float* __restrict__ x, const float* __restrict__ y)
{
    const int n = Bz * Sz * Cz;
    int i = (blockIdx.x * 256 + threadIdx.x) * 4;
    const float* src = blockIdx.y ? y : x;
    u16* ph = blockIdx.y ? g_yh : g_xh;
    u16* pl = blockIdx.y ? g_yl : g_xl;
    if (i < n) {
        float4 v = *(const float4*)&src[i];
        uint32_t h0, l0, h1, l1;
        split_pack(v.x, v.y, h0, l0);
        split_pack(v.z, v.w, h1, l1);
        *(uint2*)&ph[i] = make_uint2(h0, h1);
        *(uint2*)&pl[i] = make_uint2(l0, l1);
    }
}

// Kernel 0b: weights fp32 -> bf16 hi/lo (z selects wq/wk/wv/wf)
__global__ __launch_bounds__(256) void cvt_w(
    const float* __restrict__ wq, const float* __restrict__ wk,
    const float* __restrict__ wv, const float* __restrict__ wf)
{
    const int n = Cz * Cz;
    int i = (blockIdx.x * 256 + threadIdx.x) * 4;
    const float* src; u16* ph; u16* pl;
    switch (blockIdx.y) {
        case 0: src = wq; ph = g_wqh; pl = g_wql; break;
        case 1: src = wk; ph = g_wkh; pl = g_wkl; break;
        case 2: src = wv; ph = g_wvh; pl = g_wvl; break;
        default: src = wf; ph = g_wfh; pl = g_wfl; break;
    }
    if (i < n) {
        float4 v = *(const float4*)&src[i];
        uint32_t h0, l0, h1, l1;
        split_pack(v.x, v.y, h0, l0);
        split_pack(v.z, v.w, h1, l1);
        *(uint2*)&ph[i] = make_uint2(h0, h1);
        *(uint2*)&pl[i] = make_uint2(l0, l1);
    }
}

// ---------------------------------------------------------------------------
// Shared-memory geometry
// ---------------------------------------------------------------------------
#define PA 40     // A tile pitch (32 + 8 pad), bf16 elems
#define PB 136    // B tile pitch (128 + 8 pad)
#define PV 72     // v tile pitch (64 + 8 pad)

#define PRJ_APB   10240                 // one A plane: 128*40*2
#define PRJ_BOFF  20480
#define PRJ_BPB   8704                  // one B plane: 32*136*2
#define PRJ_STRIDE 37888
#define PROJ_SMEM (2 * PRJ_STRIDE)      // 74 KB -> 2 CTAs/SM

// cv: 1 head/CTA, 256-row A tile (256x32 hi/lo), B = v 32x64 hi/lo
#define CV_APB   20480                  // one A plane: 256*40*2
#define CV_BOFF  40960
#define CV_BPB   4608                   // one B plane: 32*72*2
#define CV_STRIDE 50176
#define CV_SMEM  (2 * CV_STRIDE)        // 98 KB -> 2 CTAs/SM

// stage one (A 128x32, B 32x128) chunk pair of hi/lo planes via cp.async
__device__ __forceinline__ void stage_prj(
    const u16* __restrict__ Ah, const u16* __restrict__ Al,
    const u16* __restrict__ Bh, const u16* __restrict__ Bl,
    uint32_t base, int m0, int n0, int k0, int tid)
{
    int row = tid >> 1, half = tid & 1;
    size_t ga = (size_t)(m0 + row) * Cz + k0 + half * 16;
    uint32_t da = base + (row * PA + half * 16) * 2;
    cpa16(da, Ah + ga);               cpa16(da + 16, Ah + ga + 8);
    cpa16(da + PRJ_APB, Al + ga);     cpa16(da + PRJ_APB + 16, Al + ga + 8);
    int br = tid >> 3, seg = tid & 7;
    size_t gb = (size_t)(k0 + br) * Cz + n0 + seg * 8;
    uint32_t db = base + PRJ_BOFF + (br * PB + seg * 8) * 2;
    cpa16(db, Bh + gb);               cpa16(db + 128, Bh + gb + 64);
    cpa16(db + PRJ_BPB, Bl + gb);     cpa16(db + PRJ_BPB + 128, Bl + gb + 64);
}

// one 32-k chunk of 3-term split MMAs (warp tile 64x32, frags 4x4)
__device__ __forceinline__ void mma_chunk(
    float d[4][4][4], uint32_t Ah, uint32_t Al, uint32_t Bh, uint32_t Bl,
    int pitchB, int wm64, int wn32, int lane)
{
    #pragma unroll
    for (int k16 = 0; k16 < 32; k16 += 16) {
        uint32_t ah[4][4], al[4][4];
        #pragma unroll
        for (int mf = 0; mf < 4; ++mf) {
            int mr = wm64 + mf * 16 + (lane & 15);
            int kc = k16 + ((lane >> 4) << 3);
            ldsm4(ah[mf], Ah + (mr * PA + kc) * 2);
            ldsm4(al[mf], Al + (mr * PA + kc) * 2);
        }
        uint32_t bh[4][2], bl[4][2];
        #pragma unroll
        for (int nf2 = 0; nf2 < 2; ++nf2) {
            int kr = k16 + (lane & 7) + ((lane >> 3) & 1) * 8;
            int nc = wn32 + nf2 * 16 + ((lane >> 4) << 3);
            uint32_t t[4];
            ldsm4t(t, Bh + (kr * pitchB + nc) * 2);
            bh[nf2 * 2][0] = t[0]; bh[nf2 * 2][1] = t[1];
            bh[nf2 * 2 + 1][0] = t[2]; bh[nf2 * 2 + 1][1] = t[3];
            ldsm4t(t, Bl + (kr * pitchB + nc) * 2);
            bl[nf2 * 2][0] = t[0]; bl[nf2 * 2][1] = t[1];
            bl[nf2 * 2 + 1][0] = t[2]; bl[nf2 * 2 + 1][1] = t[3];
        }
        #pragma unroll
        for (int mf = 0; mf < 4; ++mf)
            #pragma unroll
            for (int nf = 0; nf < 4; ++nf) {
                mma16816(d[mf][nf], ah[mf], bh[nf]);
                mma16816(d[mf][nf], ah[mf], bl[nf]);
                mma16816(d[mf][nf], al[mf], bh[nf]);
            }
    }
}

// 2-stage double-buffered mainloop: K = kiters*32
__device__ __forceinline__ void gemm_main(
    float d[4][4][4], const u16* Ah, const u16* Al,
    const u16* Bh, const u16* Bl,
    uint32_t sb, int m0, int n0, int tid, int lane, int wm, int wn, int kiters)
{
    stage_prj(Ah, Al, Bh, Bl, sb, m0, n0, 0, tid);
    cpa_commit();
    for (int i = 0; i < kiters; ++i) {
        const int p = i & 1;
        if (i + 1 < kiters)
            stage_prj(Ah, Al, Bh, Bl, sb + ((i + 1) & 1) * PRJ_STRIDE,
                      m0, n0, (i + 1) * 32, tid);
        cpa_commit();
        cpa_wait1();
        __syncthreads();
        uint32_t base = sb + p * PRJ_STRIDE;
        mma_chunk(d, base, base + PRJ_APB, base + PRJ_BOFF, base + PRJ_BOFF + PRJ_BPB,
                  PB, wm * 64, wn * 32, lane);
        __syncthreads();
    }
}

// ---------------------------------------------------------------------------
// Kernel 1: q/k/v projections. which: 0=q(y,wq) 1=k(x,wk) 2=v(y,wv)
// ---------------------------------------------------------------------------
__global__ __launch_bounds__(256, 2) void proj_mma(
    const float* __restrict__ bq, const float* __restrict__ bk,
    const float* __restrict__ bv)
{
    extern __shared__ char smc[];
    const uint32_t sb = smem_u32(smc);
    const int tid = threadIdx.x, lane = tid & 31, wid = tid >> 5;
    const int wm = wid & 1, wn = wid >> 1;
    const int which = blockIdx.z;
    const u16* Ahg = (which == 1) ? g_xh : g_yh;
    const u16* Alg = (which == 1) ? g_xl : g_yl;
    const u16* Bhg = (which == 0) ? g_wqh : (which == 1) ? g_wkh : g_wvh;
    const u16* Blg = (which == 0) ? g_wql : (which == 1) ? g_wkl : g_wvl;
    const float* bias = (which == 0) ? bq : (which == 1) ? bk : bv;
    const int m0 = blockIdx.y * 128, n0 = blockIdx.x * 128;

    float d[4][4][4] = {};
    gemm_main(d, Ahg, Alg, Bhg, Blg, sb, m0, n0, tid, lane, wm, wn, 32);

    #pragma unroll
    for (int mf = 0; mf < 4; ++mf)
        #pragma unroll
        for (int nf = 0; nf < 4; ++nf) {
            int mr = m0 + wm * 64 + mf * 16 + (lane >> 2);
            int nc = n0 + wn * 32 + nf * 8 + ((lane & 3) << 1);
            float2 bv2 = *(const float2*)&bias[nc];
            int bb = mr >> 11, s = mr & (Sz - 1);
            int h = nc >> 6, dd = nc & 63;
            size_t i0 = (((size_t)bb * Hz + h) * Sz + s) * Dz + dd;
            size_t i1 = (((size_t)bb * Hz + h) * Sz + s + 8) * Dz + dd;
            if (which == 2) {
                uint32_t hi, lo;
                split_pack(d[mf][nf][0] + bv2.x, d[mf][nf][1] + bv2.y, hi, lo);
                *(uint32_t*)&g_vh[i0] = hi; *(uint32_t*)&g_vl[i0] = lo;
                split_pack(d[mf][nf][2] + bv2.x, d[mf][nf][3] + bv2.y, hi, lo);
                *(uint32_t*)&g_vh[i1] = hi; *(uint32_t*)&g_vl[i1] = lo;
            } else {
                float* out = (which == 0) ? g_q : g_k;
                *(float2*)&out[i0] = make_float2(d[mf][nf][0] + bv2.x, d[mf][nf][1] + bv2.y);
                *(float2*)&out[i1] = make_float2(d[mf][nf][2] + bv2.x, d[mf][nf][3] + bv2.y);
            }
        }
}

// ---------------------------------------------------------------------------
// Kernel 2: cv[bh] = tanh(t*wc[h]+bc[h]) @ v[bh].
// 1 head/CTA, 256-row tiles: grid (kt=8, h=16, b=2) = 256 CTAs, 98KB smem,
// occ 2 -> staging of one CTA overlaps MMA of its SM partner.
// 8 warps: warp tile 64m x 32n over (256 x 64).
// ---------------------------------------------------------------------------
__global__ __launch_bounds__(256, 2) void cv_mma(
    const float* __restrict__ t_mat, const float* __restrict__ wc,
    const float* __restrict__ bc)
{
    extern __shared__ char smc[];
    const uint32_t sb = smem_u32(smc);
    const int tid = threadIdx.x, lane = tid & 31, wid = tid >> 5;
    const int kt = blockIdx.x, h = blockIdx.y, b = blockIdx.z;
    const int bh = b * Hz + h;
    const float wch = wc[h], bch = bc[h];
    const float* Tp = t_mat + (size_t)b * Sz * Sz + (size_t)(kt * 256) * Sz;
    const size_t vb = (size_t)bh * Sz * Dz;

    const int m0w = (wid & 3) * 64, n0w = (wid >> 2) * 32;
    const int bRow = tid >> 3, bSeg = tid & 7;

    float d[4][4][4] = {};

    auto stageA = [&](int s0, uint32_t base) {
        const float* tp = &Tp[(size_t)tid * Sz + s0];
        #pragma unroll
        for (int u = 0; u < 8; ++u) {
            float4 t4 = *(const float4*)&tp[u * 4];
            uint32_t off = (tid * PA + u * 4) * 2;
            uint32_t h0, l0, h1, l1;
            split_pack(tanh_fast(fmaf(t4.x, wch, bch)), tanh_fast(fmaf(t4.y, wch, bch)), h0, l0);
            split_pack(tanh_fast(fmaf(t4.z, wch, bch)), tanh_fast(fmaf(t4.w, wch, bch)), h1, l1);
            *(uint2*)(smc + (base + off)) = make_uint2(h0, h1);
            *(uint2*)(smc + (base + CV_APB + off)) = make_uint2(l0, l1);
        }
    };
    auto stageB = [&](int s0, uint32_t base) {
        size_t g0 = vb + (size_t)(s0 + bRow) * Dz + bSeg * 8;
        uint32_t db = sb + base + CV_BOFF + (bRow * PV + bSeg * 8) * 2;
        cpa16(db, g_vh + g0);
        cpa16(db + CV_BPB, g_vl + g0);
    };

    stageA(0, 0); stageB(0, 0);
    cpa_commit();
    for (int i = 0; i < 64; ++i) {
        const int p = i & 1;
        if (i + 1 < 64) {
            uint32_t nb = ((i + 1) & 1) * CV_STRIDE;
            stageA((i + 1) * 32, nb);
            stageB((i + 1) * 32, nb);
        }
        cpa_commit();
        cpa_wait1();
        __syncthreads();
        uint32_t base = sb + p * CV_STRIDE;
        mma_chunk(d, base, base + CV_APB, base + CV_BOFF, base + CV_BOFF + CV_BPB,
                  PV, m0w, n0w, lane);
        __syncthreads();
    }

    float* Op = g_cv + vb;
    #pragma unroll
    for (int mf = 0; mf < 4; ++mf)
        #pragma unroll
        for (int nf = 0; nf < 4; ++nf) {
            int row = kt * 256 + m0w + mf * 16 + (lane >> 2);
            int dd  = n0w + nf * 8 + ((lane & 3) << 1);
            *(float2*)&Op[(size_t)row * Dz + dd] = make_float2(d[mf][nf][0], d[mf][nf][1]);
            *(float2*)&Op[(size_t)(row + 8) * Dz + dd] = make_float2(d[mf][nf][2], d[mf][nf][3]);
        }
}

// ---------------------------------------------------------------------------
// Kernel 3: M[bh] = (1/sqrt(D)) * q[bh]^T @ cv[bh]  (64x64, K=2048), split-K x4
// ---------------------------------------------------------------------------
__global__ __launch_bounds__(256) void m_kernel()
{
    const int bh    = blockIdx.x;
    const int split = blockIdx.y;
    const float* Q   = g_q  + (size_t)bh * Sz * Dz;
    const float* CVp = g_cv + (size_t)bh * Sz * Dz;

    __shared__ float As[16][68];
    __shared__ float Bs[16][68];

    const int tid = threadIdx.x;
    const int tx = tid & 15;
    const int ty = tid >> 4;
    const int r  = tid >> 4;
    const int c4 = (tid & 15) * 4;

    float acc[4][4] = {};
    const int sBeg = split * (Sz / 4);

    for (int s0 = sBeg; s0 < sBeg + Sz / 4; s0 += 16) {
        *reinterpret_cast<float4*>(&As[r][c4]) =
            *reinterpret_cast<const float4*>(&Q[(size_t)(s0 + r) * Dz + c4]);
        *reinterpret_cast<float4*>(&Bs[r][c4]) =
            *reinterpret_cast<const float4*>(&CVp[(size_t)(s0 + r) * Dz + c4]);
        __syncthreads();
        #pragma unroll
        for (int kk = 0; kk < 16; ++kk) {
            float4 a = *reinterpret_cast<const float4*>(&As[kk][ty * 4]);
            float4 b = *reinterpret_cast<const float4*>(&Bs[kk][tx * 4]);
            float ar[4] = {a.x, a.y, a.z, a.w};
            float br[4] = {b.x, b.y, b.z, b.w};
            #pragma unroll
            for (int i = 0; i < 4; ++i)
                #pragma unroll
                for (int j = 0; j < 4; ++j)
                    acc[i][j] = fmaf(ar[i], br[j], acc[i][j]);
        }
        __syncthreads();
    }

    float* Mp = g_Mpart + ((size_t)split * BHz + bh) * Dz * Dz;
    #pragma unroll
    for (int i = 0; i < 4; ++i)
        #pragma unroll
        for (int j = 0; j < 4; ++j)
            Mp[(ty * 4 + i) * Dz + tx * 4 + j] = acc[i][j] * 0.125f;
}

// ---------------------------------------------------------------------------
// Kernel 4: att[bh] = k[bh] @ M[bh] -> merged written as bf16 hi/lo planes
// ---------------------------------------------------------------------------
__global__ __launch_bounds__(256) void att_kernel()
{
    const int bh = blockIdx.z;
    const int b  = bh >> 4;
    const int h  = bh & 15;
    const int s0 = blockIdx.y * 64;
    const float* Kp = g_k + (size_t)bh * Sz * Dz;

    __shared__ float Ms[Dz * Dz];
    __shared__ float As[16][68];

    const int tid = threadIdx.x;
    const int tx = tid & 15;
    const int ty = tid >> 4;

    const float4* P0 = reinterpret_cast<const float4*>(g_Mpart + ((size_t)0 * BHz + bh) * Dz * Dz);
    const float4* P1 = reinterpret_cast<const float4*>(g_Mpart + ((size_t)1 * BHz + bh) * Dz * Dz);
    const float4* P2 = reinterpret_cast<const float4*>(g_Mpart + ((size_t)2 * BHz + bh) * Dz * Dz);
    const float4* P3 = reinterpret_cast<const float4*>(g_Mpart + ((size_t)3 * BHz + bh) * Dz * Dz);
    #pragma unroll
    for (int it = 0; it < 4; ++it) {
        int fi = it * 256 + tid;
        float4 a = P0[fi], bb4 = P1[fi], c = P2[fi], dd = P3[fi];
        float4 rr;
        rr.x = a.x + bb4.x + c.x + dd.x;
        rr.y = a.y + bb4.y + c.y + dd.y;
        rr.z = a.z + bb4.z + c.z + dd.z;
        rr.w = a.w + bb4.w + c.w + dd.w;
        reinterpret_cast<float4*>(Ms)[fi] = rr;
    }
    __syncthreads();

    const int aRow = tid >> 2;
    const int aCol = (tid & 3) * 4;

    float acc[4][4] = {};
    #pragma unroll
    for (int kb = 0; kb < 4; ++kb) {
        float4 a4 = *reinterpret_cast<const float4*>(&Kp[(size_t)(s0 + aRow) * Dz + kb * 16 + aCol]);
        As[aCol + 0][aRow] = a4.x;
        As[aCol + 1][aRow] = a4.y;
        As[aCol + 2][aRow] = a4.z;
        As[aCol + 3][aRow] = a4.w;
        __syncthreads();
        #pragma unroll
        for (int kk = 0; kk < 16; ++kk) {
            float4 a = *reinterpret_cast<const float4*>(&As[kk][ty * 4]);
            float4 bm = *reinterpret_cast<const float4*>(&Ms[(kb * 16 + kk) * Dz + tx * 4]);
            float ar[4] = {a.x, a.y, a.z, a.w};
            float br[4] = {bm.x, bm.y, bm.z, bm.w};
            #pragma unroll
            for (int i = 0; i < 4; ++i)
                #pragma unroll
                for (int j = 0; j < 4; ++j)
                    acc[i][j] = fmaf(ar[i], br[j], acc[i][j]);
        }
        __syncthreads();
    }

    #pragma unroll
    for (int i = 0; i < 4; ++i) {
        size_t rowi = ((size_t)b * Sz + s0 + ty * 4 + i) * Cz + h * Dz + tx * 4;
        uint32_t hi, lo;
        split_pack(acc[i][0], acc[i][1], hi, lo);
        *(uint32_t*)&g_mh[rowi] = hi; *(uint32_t*)&g_ml[rowi] = lo;
        split_pack(acc[i][2], acc[i][3], hi, lo);
        *(uint32_t*)&g_mh[rowi + 2] = hi; *(uint32_t*)&g_ml[rowi + 2] = lo;
    }
}

// ---------------------------------------------------------------------------
// Kernel 5: out = mish(merged @ wf + bf).  occ-2 like proj.
// ---------------------------------------------------------------------------
__global__ __launch_bounds__(256, 2) void final_mma(
    const float* __restrict__ bf, float* __restrict__ out)
{
    extern __shared__ char smc[];
    const uint32_t sb = smem_u32(smc);
    const int tid = threadIdx.x, lane = tid & 31, wid = tid >> 5;
    const int wm = wid & 1, wn = wid >> 1;
    const int m0 = blockIdx.y * 128, n0 = blockIdx.x * 128;

    float d[4][4][4] = {};
    gemm_main(d, g_mh, g_ml, g_wfh, g_wfl, sb, m0, n0, tid, lane, wm, wn, 32);

    #pragma unroll
    for (int mf = 0; mf < 4; ++mf)
        #pragma unroll
        for (int nf = 0; nf < 4; ++nf) {
            int mr = m0 + wm * 64 + mf * 16 + (lane >> 2);
            int nc = n0 + wn * 32 + nf * 8 + ((lane & 3) << 1);
            float2 bv2 = *(const float2*)&bf[nc];
            *(float2*)&out[(size_t)mr * Cz + nc] =
                make_float2(mish_f(d[mf][nf][0] + bv2.x), mish_f(d[mf][nf][1] + bv2.y));
            *(float2*)&out[(size_t)(mr + 8) * Cz + nc] =
                make_float2(mish_f(d[mf][nf][2] + bv2.x), mish_f(d[mf][nf][3] + bv2.y));
        }
}

// ---------------------------------------------------------------------------
extern "C" void kernel_launch(void* const* d_in, const int* in_sizes, int n_in,
                              void* d_out, int out_size)
{
    const float* x  = (const float*)d_in[0];
    const float* y  = (const float*)d_in[1];
    const float* t  = (const float*)d_in[2];
    const float* wq = (const float*)d_in[3];
    const float* bq = (const float*)d_in[4];
    const float* wk = (const float*)d_in[5];
    const float* bk = (const float*)d_in[6];
    const float* wv = (const float*)d_in[7];
    const float* bv = (const float*)d_in[8];
    const float* wc = (const float*)d_in[9];
    const float* bc = (const float*)d_in[10];
    const float* wf = (const float*)d_in[11];
    const float* bf = (const float*)d_in[12];
    float* out = (float*)d_out;

    cudaFuncSetAttribute(proj_mma,  cudaFuncAttributeMaxDynamicSharedMemorySize, PROJ_SMEM);
    cudaFuncSetAttribute(cv_mma,    cudaFuncAttributeMaxDynamicSharedMemorySize, CV_SMEM);
    cudaFuncSetAttribute(final_mma, cudaFuncAttributeMaxDynamicSharedMemorySize, PROJ_SMEM);

    const int nAct = Bz * Sz * Cz;
    const int nW   = Cz * Cz;
    cvt_act<<<dim3(nAct / 1024, 2), 256>>>(x, y);
    cvt_w<<<dim3(nW / 1024, 4), 256>>>(wq, wk, wv, wf);

    // q,k,v projections
    proj_mma<<<dim3(Cz / 128, (Bz * Sz) / 128, 3), 256, PROJ_SMEM>>>(bq, bk, bv);
    // cv = tanh(t*wc+bc) @ v  (1 head/CTA, 256-row tiles, occ 2)
    cv_mma<<<dim3(8, Hz, Bz), 256, CV_SMEM>>>(t, wc, bc);
    // M = q^T @ cv / sqrt(D), split-K x4
    m_kernel<<<dim3(BHz, 4), 256>>>();
    // att = k @ M -> merged bf16 planes
    att_kernel<<<dim3(1, Sz / 64, BHz), 256>>>();
    // out = mish(merged @ wf + bf)
    final_mma<<<dim3(Cz / 128, (Bz * Sz) / 128), 256, PROJ_SMEM>>>(bf, out);
}